// round 3
// baseline (speedup 1.0000x reference)
#include <cuda_runtime.h>

// ISTA deconvolution, fused per-row kernel (round 3).
// - Single pair-planar SMEM array (even-start pairs only); odd-phase operand
//   pairs derived in registers via 2 MOVs: O[p] = (E[p].hi, E[p+1].lo).
// - h stored interleaved-duplicated: one LDS.128 per k-pair yields
//   (h[2m],h[2m]),(h[2m+1],h[2m+1]).
// - Closed-form ISTA epilogue: x_T = T*sign(su)*max(|su|-lambda,0).
// - launch_bounds(256,4): 64-reg cap, 4 CTAs/SM, 32 warps.

#define BDIM 4096
#define LDIM 4096
#define KW   128
#define NTH  256
#define PPL8 266                 // ull per plane
#define NPAIR_ULL (8 * PPL8)     // 2128
#define LAMBDA 0.1f
#define TITER  5.0f

typedef unsigned long long ull;

__device__ __forceinline__ ull pk2(float lo, float hi) {
    ull r;
    asm("mov.b64 %0, {%1, %2};" : "=l"(r) : "f"(lo), "f"(hi));
    return r;
}
__device__ __forceinline__ void unpk2(ull v, float& lo, float& hi) {
    asm("mov.b64 {%0, %1}, %2;" : "=f"(lo), "=f"(hi) : "l"(v));
}
__device__ __forceinline__ ull fma2(ull a, ull b, ull c) {
    ull d;
    asm("fma.rn.f32x2 %0, %1, %2, %3;" : "=l"(d) : "l"(a), "l"(b), "l"(c));
    return d;
}
// (hi(a), lo(b)) -> one aligned pair; halves of a/b are just register halves,
// so this costs 2 MOVs after copy-propagation.
__device__ __forceinline__ ull cross(ull a, ull b) {
    ull r;
    asm("{\n\t"
        ".reg .b32 al, ah, bl, bh;\n\t"
        "mov.b64 {al, ah}, %1;\n\t"
        "mov.b64 {bl, bh}, %2;\n\t"
        "mov.b64 %0, {ah, bl};\n\t"
        "}" : "=l"(r) : "l"(a), "l"(b));
    return r;
}

// ull index of pair p = 8t + c in the pair-planar array.
#define PIDX(c, t) ((((c) & 7) * PPL8) + ((c) >> 3) + (t))

// 16 outputs (8 f32x2 accumulators) per thread. E ring of 8 LDS-fed slots;
// O ring built by register crosses.
__device__ __forceinline__ void conv16(const ull* __restrict__ ep,
                                       const ull* __restrict__ hq,
                                       int t, ull* __restrict__ acc)
{
    ull E[8], O[8];
#pragma unroll
    for (int c = 0; c < 8; c++) E[c] = ep[c * PPL8 + t];
#pragma unroll
    for (int c = 0; c < 7; c++) O[c] = cross(E[c], E[(c + 1) & 7]);
#pragma unroll
    for (int q = 0; q < 8; q++) acc[q] = 0ull;

#pragma unroll
    for (int m = 0; m < KW / 2; m++) {
        ulonglong2 hh = *reinterpret_cast<const ulonglong2*>(hq + 2 * m);
        ull Enew = ep[PIDX(m + 8, t)];
        O[(m + 7) & 7] = cross(E[(m + 7) & 7], Enew);
#pragma unroll
        for (int q = 0; q < 8; q++) {
            acc[q] = fma2(E[(m + q) & 7], hh.x, acc[q]);
            acc[q] = fma2(O[(m + q) & 7], hh.y, acc[q]);
        }
        E[m & 7] = Enew;
    }
}

__global__ __launch_bounds__(NTH, 4)
void ista_row_kernel(const float* __restrict__ y,
                     const float* __restrict__ h,
                     const float* __restrict__ step,
                     float* __restrict__ out)
{
    __shared__ __align__(16) ull sh_ep[NPAIR_ULL];
    __shared__ __align__(16) ull sh_h[KW];    // dup pairs, natural order
    __shared__ __align__(16) ull sh_hr[KW];   // dup pairs, reversed kernel

    const int t = threadIdx.x;
    const int row = blockIdx.x;
    const float* yr = y + (long long)row * LDIM;
    const float s = __ldg(step);

    // Zero the pair array (pads + overshoot), load dup'd h / h_rev.
    for (int i = t; i < NPAIR_ULL; i += NTH) sh_ep[i] = 0ull;
    if (t < KW) {
        float hv = h[t];
        sh_h[t] = pk2(hv, hv);
        sh_hr[KW - 1 - t] = pk2(hv, hv);
    }
    __syncthreads();

    // Stage y (16 floats/thread) into pair-planar layout: xp[j] = y[j-63].
    {
        float v[16];
        const float4* y4 = reinterpret_cast<const float4*>(yr + 16 * t);
#pragma unroll
        for (int i = 0; i < 4; i++) {
            float4 f = __ldg(y4 + i);
            v[4 * i + 0] = f.x; v[4 * i + 1] = f.y;
            v[4 * i + 2] = f.z; v[4 * i + 3] = f.w;
        }
        float* epf = reinterpret_cast<float*>(sh_ep);
#pragma unroll
        for (int i = 0; i < 7; i++)
            sh_ep[PIDX(32 + i, t)] = pk2(v[2 * i + 1], v[2 * i + 2]);
        epf[2 * PIDX(31, t) + 1] = v[0];
        epf[2 * PIDX(39, t) + 0] = v[15];
    }
    __syncthreads();

    // Stage 1: conv(y, h); residual = y - conv (y pairs re-derived from SMEM).
    ull acc[8];
    conv16(sh_ep, sh_h, t, acc);

    ull r2[8];
    {
        const ull neg1 = pk2(-1.0f, -1.0f);
        ull prev = sh_ep[PIDX(31, t)];
#pragma unroll
        for (int q = 0; q < 8; q++) {
            ull nxt = sh_ep[PIDX(32 + q, t)];
            ull yp = cross(prev, nxt);            // (y[16t+2q], y[16t+2q+1])
            r2[q] = fma2(acc[q], neg1, yp);
            prev = nxt;
        }
    }
    __syncthreads();

    // Overwrite pair array with residual (identical padding geometry).
    {
        float* epf = reinterpret_cast<float*>(sh_ep);
        float lo[8], hi[8];
#pragma unroll
        for (int q = 0; q < 8; q++) unpk2(r2[q], lo[q], hi[q]);
#pragma unroll
        for (int i = 0; i < 7; i++)
            sh_ep[PIDX(32 + i, t)] = pk2(hi[i], lo[i + 1]);
        epf[2 * PIDX(31, t) + 1] = lo[0];
        epf[2 * PIDX(39, t) + 0] = hi[7];
    }
    __syncthreads();

    // Stage 2: conv(resid, h_rev) + closed-form ISTA epilogue.
    conv16(sh_ep, sh_hr, t, acc);

    float xo[16];
#pragma unroll
    for (int q = 0; q < 8; q++) {
        float u0, u1;
        unpk2(acc[q], u0, u1);
        float a0 = s * u0;
        float a1 = s * u1;
        xo[2 * q + 0] = copysignf(TITER * fmaxf(fabsf(a0) - LAMBDA, 0.0f), a0);
        xo[2 * q + 1] = copysignf(TITER * fmaxf(fabsf(a1) - LAMBDA, 0.0f), a1);
    }
    float4* o4 = reinterpret_cast<float4*>(out + (long long)row * LDIM + 16 * t);
#pragma unroll
    for (int i = 0; i < 4; i++)
        o4[i] = make_float4(xo[4 * i], xo[4 * i + 1], xo[4 * i + 2], xo[4 * i + 3]);
}

extern "C" void kernel_launch(void* const* d_in, const int* in_sizes, int n_in,
                              void* d_out, int out_size)
{
    const float* y = nullptr;
    const float* h = nullptr;
    const float* s = nullptr;
    for (int i = 0; i < n_in; i++) {
        if (in_sizes[i] == BDIM * LDIM)      y = (const float*)d_in[i];
        else if (in_sizes[i] == KW)          h = (const float*)d_in[i];
        else if (in_sizes[i] == 1)           s = (const float*)d_in[i];
    }
    ista_row_kernel<<<BDIM, NTH>>>(y, h, s, (float*)d_out);
}

// round 5
// speedup vs baseline: 1.3210x; 1.3210x over previous
#include <cuda_runtime.h>

// ISTA deconvolution, fused per-row kernel (round 5 = round 4 with FIXED pad zeroing).
// - Two pair-planar SMEM arrays (even-start pairs E, odd-start pairs O); every
//   hot-loop operand is a conflict-free LDS.64 directly into an f32x2 register
//   pair (NO register-level lane crossing — that costs real ALU movs on sm_103a).
// - h stored as interleaved duplicated ull2: sh_h[m] = ((h[2m],h[2m]), (h[2m+1],h[2m+1])),
//   one LDS.128 per k-pair, prefetched one iteration ahead.
// - Pad zeroing done in PAIR space: pair p lives at (p&7)*PPL8 + (p>>3), so
//   head pads are offsets [0,4) of all 8 planes, tail pads offsets [259,266).
// - Closed-form ISTA epilogue: x_T = T*sign(su)*max(|su|-lambda, 0).
// - __launch_bounds__(256,4): 64-reg target, 4 CTAs/SM, 32 warps.

#define BDIM 4096
#define LDIM 4096
#define KW   128
#define NTH  256
#define PPL8 266                 // ull per plane
#define NPAIR_ULL (8 * PPL8)     // 2128 ull per pair array
#define LAMBDA 0.1f
#define TITER  5.0f

typedef unsigned long long ull;

__device__ __forceinline__ ull pk2(float lo, float hi) {
    ull r;
    asm("mov.b64 %0, {%1, %2};" : "=l"(r) : "f"(lo), "f"(hi));
    return r;
}
__device__ __forceinline__ void unpk2(ull v, float& lo, float& hi) {
    asm("mov.b64 {%0, %1}, %2;" : "=f"(lo), "=f"(hi) : "l"(v));
}
__device__ __forceinline__ ull fma2(ull a, ull b, ull c) {
    ull d;
    asm("fma.rn.f32x2 %0, %1, %2, %3;" : "=l"(d) : "l"(a), "l"(b), "l"(c));
    return d;
}

// ull index of pair p = 8t + c inside a pair-planar array.
#define PIDX(c, t) ((((c) & 7) * PPL8) + ((c) >> 3) + (t))

// 16 outputs (8 f32x2 accumulators) per thread; E/O rings are LDS.64-fed,
// h pair-of-dup-pairs prefetched one iteration ahead.
__device__ __forceinline__ void conv16(const ull* __restrict__ ep,
                                       const ull* __restrict__ op,
                                       const ulonglong2* __restrict__ hq,
                                       int t, ull* __restrict__ acc)
{
    ull E[8], O[8];
#pragma unroll
    for (int c = 0; c < 8; c++) {
        E[c] = ep[c * PPL8 + t];
        O[c] = op[c * PPL8 + t];
    }
#pragma unroll
    for (int q = 0; q < 8; q++) acc[q] = 0ull;

    ulonglong2 hh = hq[0];
#pragma unroll
    for (int m = 0; m < KW / 2; m++) {
        ull Enew = 0ull, Onew = 0ull;
        ulonglong2 hn = hh;
        if (m < KW / 2 - 1) {
            Enew = ep[PIDX(m + 8, t)];
            Onew = op[PIDX(m + 8, t)];
            hn = hq[m + 1];
        }
#pragma unroll
        for (int q = 0; q < 8; q++) {
            acc[q] = fma2(E[(m + q) & 7], hh.x, acc[q]);
            acc[q] = fma2(O[(m + q) & 7], hh.y, acc[q]);
        }
        if (m < KW / 2 - 1) {
            E[m & 7] = Enew;
            O[m & 7] = Onew;
        }
        hh = hn;
    }
}

__global__ __launch_bounds__(NTH, 4)
void ista_row_kernel(const float* __restrict__ y,
                     const float* __restrict__ h,
                     const float* __restrict__ step,
                     float* __restrict__ out)
{
    __shared__ __align__(16) ull sh_ep[NPAIR_ULL];
    __shared__ __align__(16) ull sh_op[NPAIR_ULL];
    __shared__ __align__(16) ulonglong2 sh_h[KW / 2];   // dup pairs, fwd
    __shared__ __align__(16) ulonglong2 sh_hr[KW / 2];  // dup pairs, reversed

    const int t = threadIdx.x;
    const int row = blockIdx.x;
    const float* yr = y + (long long)row * LDIM;
    const float s = __ldg(step);

    // Zero ONLY the pad/overshoot regions — in PAIR space.
    // Head: pairs [0,32) -> offsets [0,4) of each plane.
    if (t < 32) {
        int pl = t >> 2, off = t & 3;
        sh_ep[pl * PPL8 + off] = 0ull;
        sh_op[pl * PPL8 + off] = 0ull;
    }
    // Tail: conv reads pairs up to 2110; staged data ends at 2079 (ep) / 2078 (op).
    // Zero offsets [259,266) of each plane (pairs 2072..2127); staged ones are
    // overwritten below, after the sync.
    if (t < 56) {
        int pl = t / 7, off = 259 + (t % 7);
        sh_ep[pl * PPL8 + off] = 0ull;
        sh_op[pl * PPL8 + off] = 0ull;
    }
    if (t < KW / 2) {
        float a0 = h[2 * t], a1 = h[2 * t + 1];
        sh_h[t] = make_ulonglong2(pk2(a0, a0), pk2(a1, a1));
        float b0 = h[KW - 1 - 2 * t], b1 = h[KW - 2 - 2 * t];  // reversed kernel
        sh_hr[t] = make_ulonglong2(pk2(b0, b0), pk2(b1, b1));
    }
    __syncthreads();

    // Stage y (16 floats/thread) into pair arrays: xp[j] = y[j-63].
    // thread t owns y[16t..16t+15] -> xp[63+16t .. 78+16t].
    {
        float v[16];
        const float4* y4 = reinterpret_cast<const float4*>(yr + 16 * t);
#pragma unroll
        for (int i = 0; i < 4; i++) {
            float4 f = __ldg(y4 + i);
            v[4 * i + 0] = f.x; v[4 * i + 1] = f.y;
            v[4 * i + 2] = f.z; v[4 * i + 3] = f.w;
        }
#pragma unroll
        for (int i = 0; i < 8; i++)   // opairs[8t+31+i] = (v[2i], v[2i+1])
            sh_op[PIDX(31 + i, t)] = pk2(v[2 * i], v[2 * i + 1]);
#pragma unroll
        for (int i = 0; i < 7; i++)   // epairs[8t+32+i] = (v[2i+1], v[2i+2])
            sh_ep[PIDX(32 + i, t)] = pk2(v[2 * i + 1], v[2 * i + 2]);
        float* epf = reinterpret_cast<float*>(sh_ep);
        epf[2 * PIDX(31, t) + 1] = v[0];    // hi of epairs[8t+31]
        epf[2 * PIDX(39, t) + 0] = v[15];   // lo of epairs[8t+39]
    }
    __syncthreads();

    // Stage 1: conv(y, h); residual = y - conv (y pairs re-read before sync).
    ull acc[8];
    conv16(sh_ep, sh_op, sh_h, t, acc);

    ull r2[8];
    {
        const ull neg1 = pk2(-1.0f, -1.0f);
#pragma unroll
        for (int q = 0; q < 8; q++) {
            ull yp = sh_op[PIDX(31 + q, t)];   // (y[16t+2q], y[16t+2q+1])
            r2[q] = fma2(acc[q], neg1, yp);    // resid = y - conv
        }
    }
    __syncthreads();

    // Overwrite pair arrays with residual (identical padding geometry;
    // pad regions remain zero — never touched).
    {
        float lo[8], hi[8];
#pragma unroll
        for (int q = 0; q < 8; q++) unpk2(r2[q], lo[q], hi[q]);
#pragma unroll
        for (int q = 0; q < 8; q++)
            sh_op[PIDX(31 + q, t)] = r2[q];
#pragma unroll
        for (int i = 0; i < 7; i++)
            sh_ep[PIDX(32 + i, t)] = pk2(hi[i], lo[i + 1]);
        float* epf = reinterpret_cast<float*>(sh_ep);
        epf[2 * PIDX(31, t) + 1] = lo[0];
        epf[2 * PIDX(39, t) + 0] = hi[7];
    }
    __syncthreads();

    // Stage 2: conv(resid, h_rev) + closed-form ISTA epilogue.
    conv16(sh_ep, sh_op, sh_hr, t, acc);

    float xo[16];
#pragma unroll
    for (int q = 0; q < 8; q++) {
        float u0, u1;
        unpk2(acc[q], u0, u1);
        float a0 = s * u0;
        float a1 = s * u1;
        xo[2 * q + 0] = copysignf(TITER * fmaxf(fabsf(a0) - LAMBDA, 0.0f), a0);
        xo[2 * q + 1] = copysignf(TITER * fmaxf(fabsf(a1) - LAMBDA, 0.0f), a1);
    }
    float4* o4 = reinterpret_cast<float4*>(out + (long long)row * LDIM + 16 * t);
#pragma unroll
    for (int i = 0; i < 4; i++)
        o4[i] = make_float4(xo[4 * i], xo[4 * i + 1], xo[4 * i + 2], xo[4 * i + 3]);
}

extern "C" void kernel_launch(void* const* d_in, const int* in_sizes, int n_in,
                              void* d_out, int out_size)
{
    const float* y = nullptr;
    const float* h = nullptr;
    const float* s = nullptr;
    for (int i = 0; i < n_in; i++) {
        if (in_sizes[i] == BDIM * LDIM)      y = (const float*)d_in[i];
        else if (in_sizes[i] == KW)          h = (const float*)d_in[i];
        else if (in_sizes[i] == 1)           s = (const float*)d_in[i];
    }
    ista_row_kernel<<<BDIM, NTH>>>(y, h, s, (float*)d_out);
}

// round 6
// speedup vs baseline: 1.3389x; 1.0135x over previous
#include <cuda_runtime.h>

// ISTA deconvolution, fused per-row kernel (round 6: tap-parity split).
// Single pair-planar E array. Even-tap partials accumulate into output-aligned
// pairs; odd-tap partials accumulate into pairs staggered by one scalar:
//   eacc[q] = sum_m h[2m]   * E[8t+q+m]      -> (c_e[16t+2q],   c_e[16t+2q+1])
//   oa[j]   = sum_m h[2m+1] * E[8t+j+m]      -> (c_o[16t+2j-1], c_o[16t+2j]),  j=0..8
// Both read ONLY E pairs (same operand register feeds both FFMA2s), so the
// hot loop needs exactly one LDS.64 ring refill + one broadcast LDS.128 (h)
// per k-pair. The one-scalar stagger is resolved once per conv with scalar
// FADDs on unpacked register halves (free), never inside the loop.
// out[n] = c_e[n] + c_o[n];  u[2q] = lo(eacc[q]) + hi(oa[q]),
//                            u[2q+1] = hi(eacc[q]) + lo(oa[q+1]).
// Closed-form ISTA epilogue: x_T = T*sign(su)*max(|su|-lambda, 0).

#define BDIM 4096
#define LDIM 4096
#define KW   128
#define NTH  256
#define PPL8 266                 // ull per plane
#define NPAIR_ULL (8 * PPL8)     // 2128
#define LAMBDA 0.1f
#define TITER  5.0f

typedef unsigned long long ull;

__device__ __forceinline__ ull pk2(float lo, float hi) {
    ull r;
    asm("mov.b64 %0, {%1, %2};" : "=l"(r) : "f"(lo), "f"(hi));
    return r;
}
__device__ __forceinline__ void unpk2(ull v, float& lo, float& hi) {
    asm("mov.b64 {%0, %1}, %2;" : "=f"(lo), "=f"(hi) : "l"(v));
}
__device__ __forceinline__ ull fma2(ull a, ull b, ull c) {
    ull d;
    asm("fma.rn.f32x2 %0, %1, %2, %3;" : "=l"(d) : "l"(a), "l"(b), "l"(c));
    return d;
}

// ull index of pair p = 8t + c inside the pair-planar array.
#define PIDX(c, t) ((((c) & 7) * PPL8) + ((c) >> 3) + (t))

// Tap-parity-split convolution: 8 even accumulators + 9 odd accumulators.
// E ring of 8 slots, one LDS.64 refill per m (reads pairs up to 8t+71,
// covered by tail zero-pads, so no guard). h prefetched one iter ahead
// (hq must have >= 65 entries; entry 64 is a zero pad).
__device__ __forceinline__ void conv_split(const ull* __restrict__ ep,
                                           const ulonglong2* __restrict__ hq,
                                           int t,
                                           ull* __restrict__ eacc,
                                           ull* __restrict__ oa)
{
    ull E[8];
#pragma unroll
    for (int c = 0; c < 8; c++) E[c] = ep[c * PPL8 + t];
#pragma unroll
    for (int q = 0; q < 8; q++) eacc[q] = 0ull;
#pragma unroll
    for (int j = 0; j < 9; j++) oa[j] = 0ull;

    ulonglong2 hh = hq[0];
#pragma unroll
    for (int m = 0; m < KW / 2; m++) {
        ull Enew = ep[PIDX(m + 8, t)];       // pair 8t+m+8
        ulonglong2 hn = hq[m + 1];           // zero-pad entry on last iter
#pragma unroll
        for (int q = 0; q < 8; q++) {
            ull Eq = E[(m + q) & 7];         // pair 8t+m+q — feeds BOTH accs
            eacc[q] = fma2(Eq, hh.x, eacc[q]);
            oa[q]   = fma2(Eq, hh.y, oa[q]);
        }
        oa[8] = fma2(Enew, hh.y, oa[8]);
        E[m & 7] = Enew;
        hh = hn;
    }
}

__global__ __launch_bounds__(NTH, 3)
void ista_row_kernel(const float* __restrict__ y,
                     const float* __restrict__ h,
                     const float* __restrict__ step,
                     float* __restrict__ out)
{
    __shared__ __align__(16) ull sh_ep[NPAIR_ULL];
    __shared__ __align__(16) ulonglong2 sh_h[KW / 2 + 1];   // dup pairs, fwd (+pad)
    __shared__ __align__(16) ulonglong2 sh_hr[KW / 2 + 1];  // dup pairs, rev (+pad)

    const int t = threadIdx.x;
    const int row = blockIdx.x;
    const float* yr = y + (long long)row * LDIM;
    const float s = __ldg(step);

    // Zero pad/overshoot regions in PAIR space.
    // Head: pairs [0,32) -> offsets [0,4) of each plane.
    if (t < 32) {
        int pl = t >> 2, off = t & 3;
        sh_ep[pl * PPL8 + off] = 0ull;
    }
    // Tail: conv reads pairs up to 2111; staged data ends at pair 2079.
    // Zero offsets [259,266) of each plane (pairs 2072..2127); staged ones
    // are overwritten after the first sync.
    if (t < 56) {
        int pl = t / 7, off = 259 + (t % 7);
        sh_ep[pl * PPL8 + off] = 0ull;
    }
    if (t < KW / 2) {
        float a0 = h[2 * t], a1 = h[2 * t + 1];
        sh_h[t] = make_ulonglong2(pk2(a0, a0), pk2(a1, a1));
        float b0 = h[KW - 1 - 2 * t], b1 = h[KW - 2 - 2 * t];  // reversed
        sh_hr[t] = make_ulonglong2(pk2(b0, b0), pk2(b1, b1));
    }
    if (t == KW / 2) {  // zero pad entries for unguarded prefetch
        sh_h[KW / 2]  = make_ulonglong2(0ull, 0ull);
        sh_hr[KW / 2] = make_ulonglong2(0ull, 0ull);
    }
    __syncthreads();

    // Stage y (16 floats/thread) into E pairs: xp[j] = y[j-63].
    // thread t owns y[16t..16t+15] -> xp[16t+63 .. 16t+78].
    {
        float v[16];
        const float4* y4 = reinterpret_cast<const float4*>(yr + 16 * t);
#pragma unroll
        for (int i = 0; i < 4; i++) {
            float4 f = __ldg(y4 + i);
            v[4 * i + 0] = f.x; v[4 * i + 1] = f.y;
            v[4 * i + 2] = f.z; v[4 * i + 3] = f.w;
        }
#pragma unroll
        for (int i = 0; i < 7; i++)   // epairs[8t+32+i] = (v[2i+1], v[2i+2])
            sh_ep[PIDX(32 + i, t)] = pk2(v[2 * i + 1], v[2 * i + 2]);
        float* epf = reinterpret_cast<float*>(sh_ep);
        epf[2 * PIDX(31, t) + 1] = v[0];    // hi of epairs[8t+31]
        epf[2 * PIDX(39, t) + 0] = v[15];   // lo of epairs[8t+39]
    }
    __syncthreads();

    // ---- Stage 1: conv(y, h), residual = y - (c_e + c_o) ----
    ull eacc[8], oa[9];
    conv_split(sh_ep, sh_h, t, eacc, oa);

    // Reload y (global, L1-hot) — issued before the sync, consumed after.
    float v[16];
    {
        const float4* y4 = reinterpret_cast<const float4*>(yr + 16 * t);
#pragma unroll
        for (int i = 0; i < 4; i++) {
            float4 f = __ldg(y4 + i);
            v[4 * i + 0] = f.x; v[4 * i + 1] = f.y;
            v[4 * i + 2] = f.z; v[4 * i + 3] = f.w;
        }
    }
    __syncthreads();   // all E reads done before we overwrite with residual

    float ro[16];
#pragma unroll
    for (int q = 0; q < 8; q++) {
        float el, eh, ol0, oh0, ol1, oh1;
        unpk2(eacc[q], el, eh);
        unpk2(oa[q],     ol0, oh0);   // (c_o[16t+2q-1], c_o[16t+2q])
        unpk2(oa[q + 1], ol1, oh1);   // (c_o[16t+2q+1], c_o[16t+2q+2])
        ro[2 * q + 0] = v[2 * q + 0] - (el + oh0);
        ro[2 * q + 1] = v[2 * q + 1] - (eh + ol1);
    }

    // Write residual into E pairs (identical geometry; pads stay zero).
#pragma unroll
    for (int i = 0; i < 7; i++)
        sh_ep[PIDX(32 + i, t)] = pk2(ro[2 * i + 1], ro[2 * i + 2]);
    {
        float* epf = reinterpret_cast<float*>(sh_ep);
        epf[2 * PIDX(31, t) + 1] = ro[0];
        epf[2 * PIDX(39, t) + 0] = ro[15];
    }
    __syncthreads();

    // ---- Stage 2: conv(resid, h_rev) + closed-form ISTA epilogue ----
    conv_split(sh_ep, sh_hr, t, eacc, oa);

    float xo[16];
#pragma unroll
    for (int q = 0; q < 8; q++) {
        float el, eh, ol0, oh0, ol1, oh1;
        unpk2(eacc[q], el, eh);
        unpk2(oa[q],     ol0, oh0);
        unpk2(oa[q + 1], ol1, oh1);
        float a0 = s * (el + oh0);
        float a1 = s * (eh + ol1);
        xo[2 * q + 0] = copysignf(TITER * fmaxf(fabsf(a0) - LAMBDA, 0.0f), a0);
        xo[2 * q + 1] = copysignf(TITER * fmaxf(fabsf(a1) - LAMBDA, 0.0f), a1);
    }
    float4* o4 = reinterpret_cast<float4*>(out + (long long)row * LDIM + 16 * t);
#pragma unroll
    for (int i = 0; i < 4; i++)
        o4[i] = make_float4(xo[4 * i], xo[4 * i + 1], xo[4 * i + 2], xo[4 * i + 3]);
}

extern "C" void kernel_launch(void* const* d_in, const int* in_sizes, int n_in,
                              void* d_out, int out_size)
{
    const float* y = nullptr;
    const float* h = nullptr;
    const float* s = nullptr;
    for (int i = 0; i < n_in; i++) {
        if (in_sizes[i] == BDIM * LDIM)      y = (const float*)d_in[i];
        else if (in_sizes[i] == KW)          h = (const float*)d_in[i];
        else if (in_sizes[i] == 1)           s = (const float*)d_in[i];
    }
    ista_row_kernel<<<BDIM, NTH>>>(y, h, s, (float*)d_out);
}